// round 9
// baseline (speedup 1.0000x reference)
#include <cuda_runtime.h>
#include <cuda_fp16.h>
#include <cuda_bf16.h>
#include <cstdint>

#define N_NODES     100000
#define HEADS       8
#define NBLK        148
#define NTHR        512
#define TOT         (NBLK * NTHR)        // 75,776 threads
#define K_TOTAL     43                   // edges per thread (ceil(3.2M / 75776))
#define SMEM_SLOTS  26
#define REG_SLOTS   17                   // 26 + 17 = 43
#define SMEM_BYTES  (SMEM_SLOTS * NTHR * 16)   // 212,992 B

// Per-(node, head) sum of exp(e). 3.2 MB. Zeroed via memset node.
__device__ float g_sums[N_NODES * HEADS];
// Monotone barrier arrival counter (never reset; generation = count / gridDim).
__device__ unsigned int g_bar_count;

__device__ __forceinline__ uint32_t h2_as_u32(__half2 h) {
    return *reinterpret_cast<uint32_t*>(&h);
}
__device__ __forceinline__ __half2 u32_as_h2(uint32_t u) {
    return *reinterpret_cast<__half2*>(&u);
}

__device__ __forceinline__ void exp8(float4& a, float4& b) {
    a.x = __expf(a.x); a.y = __expf(a.y); a.z = __expf(a.z); a.w = __expf(a.w);
    b.x = __expf(b.x); b.y = __expf(b.y); b.z = __expf(b.z); b.w = __expf(b.w);
}

__device__ __forceinline__ void ld256_cs(const float* p, float4& a, float4& b) {
    uint32_t r0, r1, r2, r3, r4, r5, r6, r7;
    asm volatile("ld.global.cs.v8.b32 {%0,%1,%2,%3,%4,%5,%6,%7}, [%8];"
                 : "=r"(r0), "=r"(r1), "=r"(r2), "=r"(r3),
                   "=r"(r4), "=r"(r5), "=r"(r6), "=r"(r7)
                 : "l"(p));
    a.x = __uint_as_float(r0); a.y = __uint_as_float(r1);
    a.z = __uint_as_float(r2); a.w = __uint_as_float(r3);
    b.x = __uint_as_float(r4); b.y = __uint_as_float(r5);
    b.z = __uint_as_float(r6); b.w = __uint_as_float(r7);
}

__device__ __forceinline__ void st256_evict_first(float* p, float4 a, float4 b) {
    asm volatile("st.global.L2::evict_first.v8.b32 [%0], {%1,%2,%3,%4,%5,%6,%7,%8};"
                 :: "l"(p),
                    "r"(__float_as_uint(a.x)), "r"(__float_as_uint(a.y)),
                    "r"(__float_as_uint(a.z)), "r"(__float_as_uint(a.w)),
                    "r"(__float_as_uint(b.x)), "r"(__float_as_uint(b.y)),
                    "r"(__float_as_uint(b.z)), "r"(__float_as_uint(b.w))
                 : "memory");
}

__device__ __forceinline__ void red_row(float* srow, float4 a, float4 b) {
    asm volatile("red.global.add.v4.f32 [%0], {%1, %2, %3, %4};"
                 :: "l"(srow), "f"(a.x), "f"(a.y), "f"(a.z), "f"(a.w) : "memory");
    asm volatile("red.global.add.v4.f32 [%0], {%1, %2, %3, %4};"
                 :: "l"(srow + 4), "f"(b.x), "f"(b.y), "f"(b.z), "f"(b.w) : "memory");
}

// Replay-safe sense-free grid barrier: monotone arrival counter; a block whose
// arrival ticket is `old` waits until count reaches (old/grid + 1) * grid.
__device__ __forceinline__ void grid_barrier() {
    __syncthreads();
    if (threadIdx.x == 0) {
        __threadfence();  // publish phase-B REDs/stores
        unsigned int old = atomicAdd(&g_bar_count, 1u);
        unsigned int target = (old / gridDim.x + 1u) * gridDim.x;
        while (*(volatile unsigned int*)&g_bar_count < target) {
            __nanosleep(128);
        }
        __threadfence();  // acquire
    }
    __syncthreads();
}

__device__ __forceinline__ uint4 pack8(float4 a, float4 b) {
    uint4 pk;
    pk.x = h2_as_u32(__floats2half2_rn(a.x, a.y));
    pk.y = h2_as_u32(__floats2half2_rn(a.z, a.w));
    pk.z = h2_as_u32(__floats2half2_rn(b.x, b.y));
    pk.w = h2_as_u32(__floats2half2_rn(b.z, b.w));
    return pk;
}

__device__ __forceinline__ void emit_out(uint4 pk, int d, float* op) {
    float2 x0 = __half22float2(u32_as_h2(pk.x));
    float2 x1 = __half22float2(u32_as_h2(pk.y));
    float2 x2 = __half22float2(u32_as_h2(pk.z));
    float2 x3 = __half22float2(u32_as_h2(pk.w));
    const float* srow = g_sums + (size_t)d * HEADS;
    // L1-bypassing loads: coherent with phase-B REDs (which write at L2 level).
    float4 s0 = __ldcg(reinterpret_cast<const float4*>(srow));
    float4 s1 = __ldcg(reinterpret_cast<const float4*>(srow + 4));
    const float eps = 1e-16f;
    float4 o0, o1;
    o0.x = __fdividef(x0.x, s0.x + eps); o0.y = __fdividef(x0.y, s0.y + eps);
    o0.z = __fdividef(x1.x, s0.z + eps); o0.w = __fdividef(x1.y, s0.w + eps);
    o1.x = __fdividef(x2.x, s1.x + eps); o1.y = __fdividef(x2.y, s1.y + eps);
    o1.z = __fdividef(x3.x, s1.z + eps); o1.w = __fdividef(x3.y, s1.w + eps);
    st256_evict_first(op, o0, o1);
}

__global__ __launch_bounds__(NTHR, 1)
void fused_softmax_kernel(const float* __restrict__ e,
                          const int* __restrict__ dst,
                          float* __restrict__ out,
                          int E) {
    extern __shared__ uint4 stash[];   // [SMEM_SLOTS][NTHR]
    const int tid = blockIdx.x * NTHR + threadIdx.x;

    uint4 rstash[REG_SLOTS];

    // ---- Phase B: read e once, exp, RED into g_sums, stash ex as fp16x8 ----
#pragma unroll 4
    for (int k = 0; k < SMEM_SLOTS; k++) {
        int i = tid + k * TOT;
        uint4 pk = make_uint4(0, 0, 0, 0);
        if (i < E) {
            int d = dst[i];                       // default policy: L2-retained for phase C
            float4 a, b;
            ld256_cs(e + (size_t)i * HEADS, a, b);
            exp8(a, b);
            red_row(g_sums + (size_t)d * HEADS, a, b);
            pk = pack8(a, b);
        }
        stash[k * NTHR + threadIdx.x] = pk;
    }
#pragma unroll
    for (int r = 0; r < REG_SLOTS; r++) {
        int i = tid + (SMEM_SLOTS + r) * TOT;
        uint4 pk = make_uint4(0, 0, 0, 0);
        if (i < E) {
            int d = dst[i];
            float4 a, b;
            ld256_cs(e + (size_t)i * HEADS, a, b);
            exp8(a, b);
            red_row(g_sums + (size_t)d * HEADS, a, b);
            pk = pack8(a, b);
        }
        rstash[r] = pk;
    }

    grid_barrier();

    // ---- Phase C: out = ex / (sums[dst] + eps) ----
#pragma unroll 4
    for (int k = 0; k < SMEM_SLOTS; k++) {
        int i = tid + k * TOT;
        if (i < E) {
            int d = dst[i];
            emit_out(stash[k * NTHR + threadIdx.x], d, out + (size_t)i * HEADS);
        }
    }
#pragma unroll
    for (int r = 0; r < REG_SLOTS; r++) {
        int i = tid + (SMEM_SLOTS + r) * TOT;
        if (i < E) {
            int d = dst[i];
            emit_out(rstash[r], d, out + (size_t)i * HEADS);
        }
    }
}

// ---------------- Fallback (E too large for on-chip stash) ----------------
#define UNROLL 4
__global__ void scatter_sum_kernel(const float* __restrict__ e,
                                   const int* __restrict__ dst, int E) {
    int base = blockIdx.x * (blockDim.x * UNROLL) + threadIdx.x;
    int d[UNROLL]; float4 va[UNROLL], vb[UNROLL];
#pragma unroll
    for (int k = 0; k < UNROLL; k++) {
        int i = base + k * blockDim.x;
        if (i < E) { d[k] = __ldcs(dst + i); ld256_cs(e + (size_t)i * HEADS, va[k], vb[k]); }
    }
#pragma unroll
    for (int k = 0; k < UNROLL; k++) {
        int i = base + k * blockDim.x;
        if (i < E) {
            float4 a = va[k], b = vb[k];
            exp8(a, b);
            red_row(g_sums + (size_t)d[k] * HEADS, a, b);
        }
    }
}
__global__ void normalize_kernel(const float* __restrict__ e,
                                 const int* __restrict__ dst,
                                 float* __restrict__ out, int E) {
    int base = blockIdx.x * (blockDim.x * UNROLL) + threadIdx.x;
    int d[UNROLL]; float4 va[UNROLL], vb[UNROLL];
#pragma unroll
    for (int k = 0; k < UNROLL; k++) {
        int i = base + k * blockDim.x;
        if (i < E) { d[k] = __ldcs(dst + i); ld256_cs(e + (size_t)i * HEADS, va[k], vb[k]); }
    }
    const float eps = 1e-16f;
#pragma unroll
    for (int k = 0; k < UNROLL; k++) {
        int i = base + k * blockDim.x;
        if (i < E) {
            float4 a = va[k], b = vb[k];
            exp8(a, b);
            const float4* srow = reinterpret_cast<const float4*>(g_sums + (size_t)d[k] * HEADS);
            float4 s0 = srow[0], s1 = srow[1], o0, o1;
            o0.x = __fdividef(a.x, s0.x + eps); o0.y = __fdividef(a.y, s0.y + eps);
            o0.z = __fdividef(a.z, s0.z + eps); o0.w = __fdividef(a.w, s0.w + eps);
            o1.x = __fdividef(b.x, s1.x + eps); o1.y = __fdividef(b.y, s1.y + eps);
            o1.z = __fdividef(b.z, s1.z + eps); o1.w = __fdividef(b.w, s1.w + eps);
            st256_evict_first(out + (size_t)i * HEADS, o0, o1);
        }
    }
}

extern "C" void kernel_launch(void* const* d_in, const int* in_sizes, int n_in,
                              void* d_out, int out_size) {
    const float* e = (const float*)d_in[0];
    const int* edge_index = (const int*)d_in[1];
    int E = in_sizes[0] / HEADS;
    const int* dst = edge_index + (size_t)E;  // edge_index[1]
    float* out = (float*)d_out;

    // Zero g_sums with a memset node (replaces the 4.5us zero kernel).
    void* sums_ptr = nullptr;
    cudaGetSymbolAddress(&sums_ptr, g_sums);
    cudaMemsetAsync(sums_ptr, 0, (size_t)N_NODES * HEADS * sizeof(float));

    if (E <= TOT * K_TOTAL) {
        cudaFuncSetAttribute(fused_softmax_kernel,
                             cudaFuncAttributeMaxDynamicSharedMemorySize, SMEM_BYTES);
        fused_softmax_kernel<<<NBLK, NTHR, SMEM_BYTES>>>(e, dst, out, E);
    } else {
        const int T = 256;
        int nBlocks = (E + T * UNROLL - 1) / (T * UNROLL);
        scatter_sum_kernel<<<nBlocks, T>>>(e, dst, E);
        normalize_kernel<<<nBlocks, T>>>(e, dst, out, E);
    }
}

// round 10
// speedup vs baseline: 1.2923x; 1.2923x over previous
#include <cuda_runtime.h>
#include <cuda_fp16.h>
#include <cuda_bf16.h>
#include <cstdint>

#define N_NODES 100000
#define HEADS   8
#define UNROLL  4

// Per-(node, head) sum of exp(e). 3.2 MB (L2-resident). Zeroed by memset node.
__device__ float g_sums[N_NODES * HEADS];

__device__ __forceinline__ void exp8(float4& a, float4& b) {
    a.x = __expf(a.x); a.y = __expf(a.y); a.z = __expf(a.z); a.w = __expf(a.w);
    b.x = __expf(b.x); b.y = __expf(b.y); b.z = __expf(b.z); b.w = __expf(b.w);
}

// 256-bit load, L2 evict_last: pin pass-1 e stream in L2 for pass-2 reuse.
__device__ __forceinline__ void ld256_evict_last(const float* p, float4& a, float4& b) {
    uint32_t r0, r1, r2, r3, r4, r5, r6, r7;
    asm volatile("ld.global.L2::evict_last.v8.b32 {%0,%1,%2,%3,%4,%5,%6,%7}, [%8];"
                 : "=r"(r0), "=r"(r1), "=r"(r2), "=r"(r3),
                   "=r"(r4), "=r"(r5), "=r"(r6), "=r"(r7)
                 : "l"(p));
    a.x = __uint_as_float(r0); a.y = __uint_as_float(r1);
    a.z = __uint_as_float(r2); a.w = __uint_as_float(r3);
    b.x = __uint_as_float(r4); b.y = __uint_as_float(r5);
    b.z = __uint_as_float(r6); b.w = __uint_as_float(r7);
}

// 256-bit load, default policy (pass 2: hit pinned lines without demoting them).
__device__ __forceinline__ void ld256(const float* p, float4& a, float4& b) {
    uint32_t r0, r1, r2, r3, r4, r5, r6, r7;
    asm volatile("ld.global.v8.b32 {%0,%1,%2,%3,%4,%5,%6,%7}, [%8];"
                 : "=r"(r0), "=r"(r1), "=r"(r2), "=r"(r3),
                   "=r"(r4), "=r"(r5), "=r"(r6), "=r"(r7)
                 : "l"(p));
    a.x = __uint_as_float(r0); a.y = __uint_as_float(r1);
    a.z = __uint_as_float(r2); a.w = __uint_as_float(r3);
    b.x = __uint_as_float(r4); b.y = __uint_as_float(r5);
    b.z = __uint_as_float(r6); b.w = __uint_as_float(r7);
}

// 256-bit store, L2 evict_first: streaming output must not displace e.
__device__ __forceinline__ void st256_evict_first(float* p, float4 a, float4 b) {
    asm volatile("st.global.L2::evict_first.v8.b32 [%0], {%1,%2,%3,%4,%5,%6,%7,%8};"
                 :: "l"(p),
                    "r"(__float_as_uint(a.x)), "r"(__float_as_uint(a.y)),
                    "r"(__float_as_uint(a.z)), "r"(__float_as_uint(a.w)),
                    "r"(__float_as_uint(b.x)), "r"(__float_as_uint(b.y)),
                    "r"(__float_as_uint(b.z)), "r"(__float_as_uint(b.w))
                 : "memory");
}

// Pass 1: red-add exp(e) into g_sums[dst]. Warp-strided 4-edge batching.
__global__ void scatter_sum_kernel(const float* __restrict__ e,
                                   const int* __restrict__ dst,
                                   int E) {
    int base = blockIdx.x * (blockDim.x * UNROLL) + threadIdx.x;

    int d[UNROLL];
    float4 va[UNROLL], vb[UNROLL];
#pragma unroll
    for (int k = 0; k < UNROLL; k++) {
        int i = base + k * blockDim.x;
        if (i < E) {
            d[k] = __ldcs(dst + i);
            ld256_evict_last(e + (size_t)i * HEADS, va[k], vb[k]);
        }
    }
#pragma unroll
    for (int k = 0; k < UNROLL; k++) {
        int i = base + k * blockDim.x;
        if (i < E) {
            float4 a = va[k], b = vb[k];
            exp8(a, b);
            float* srow = g_sums + (size_t)d[k] * HEADS;
            asm volatile("red.global.add.v4.f32 [%0], {%1, %2, %3, %4};"
                         :: "l"(srow), "f"(a.x), "f"(a.y), "f"(a.z), "f"(a.w) : "memory");
            asm volatile("red.global.add.v4.f32 [%0], {%1, %2, %3, %4};"
                         :: "l"(srow + 4), "f"(b.x), "f"(b.y), "f"(b.z), "f"(b.w) : "memory");
        }
    }
}

// Pass 2: out = exp(e) * fast_rcp(sums[dst] + eps). Reverse block order so the
// earliest pass-2 reads hit the L2-resident tail of e left by pass 1.
__global__ void normalize_kernel(const float* __restrict__ e,
                                 const int* __restrict__ dst,
                                 float* __restrict__ out,
                                 int E, int nBlocks) {
    int rb = nBlocks - 1 - blockIdx.x;
    int base = rb * ((int)blockDim.x * UNROLL) + threadIdx.x;

    int d[UNROLL];
    float4 va[UNROLL], vb[UNROLL];
#pragma unroll
    for (int k = 0; k < UNROLL; k++) {
        int i = base + k * blockDim.x;
        if (i < E) {
            d[k] = __ldcs(dst + i);
            ld256(e + (size_t)i * HEADS, va[k], vb[k]);
        }
    }
    const float eps = 1e-16f;
#pragma unroll
    for (int k = 0; k < UNROLL; k++) {
        int i = base + k * blockDim.x;
        if (i < E) {
            float4 a = va[k], b = vb[k];
            exp8(a, b);
            const float4* srow = reinterpret_cast<const float4*>(g_sums + (size_t)d[k] * HEADS);
            float4 s0 = srow[0];
            float4 s1 = srow[1];
            float4 o0, o1;
            o0.x = __fdividef(a.x, s0.x + eps); o0.y = __fdividef(a.y, s0.y + eps);
            o0.z = __fdividef(a.z, s0.z + eps); o0.w = __fdividef(a.w, s0.w + eps);
            o1.x = __fdividef(b.x, s1.x + eps); o1.y = __fdividef(b.y, s1.y + eps);
            o1.z = __fdividef(b.z, s1.z + eps); o1.w = __fdividef(b.w, s1.w + eps);
            st256_evict_first(out + (size_t)i * HEADS, o0, o1);
        }
    }
}

extern "C" void kernel_launch(void* const* d_in, const int* in_sizes, int n_in,
                              void* d_out, int out_size) {
    const float* e = (const float*)d_in[0];
    const int* edge_index = (const int*)d_in[1];
    int E = in_sizes[0] / HEADS;
    const int* dst = edge_index + (size_t)E;  // edge_index[1]
    float* out = (float*)d_out;

    // Zero g_sums via a memset graph node (replaces the ~4.5us zero kernel).
    void* sums_ptr = nullptr;
    cudaGetSymbolAddress(&sums_ptr, g_sums);
    cudaMemsetAsync(sums_ptr, 0, (size_t)N_NODES * HEADS * sizeof(float));

    const int T = 256;
    int perBlock = T * UNROLL;
    int nBlocks = (E + perBlock - 1) / perBlock;

    scatter_sum_kernel<<<nBlocks, T>>>(e, dst, E);
    normalize_kernel<<<nBlocks, T>>>(e, dst, out, E, nBlocks);
}

// round 11
// speedup vs baseline: 1.3923x; 1.0774x over previous
#include <cuda_runtime.h>
#include <cuda_fp16.h>
#include <cuda_bf16.h>
#include <cstdint>

#define N_NODES 100000
#define HEADS   8
#define UNROLL  2

// Per-(node, head) sum of exp(e). 3.2 MB (L2-resident). Zeroed by memset node.
__device__ float g_sums[N_NODES * HEADS];

__device__ __forceinline__ void exp8(float4& a, float4& b) {
    a.x = __expf(a.x); a.y = __expf(a.y); a.z = __expf(a.z); a.w = __expf(a.w);
    b.x = __expf(b.x); b.y = __expf(b.y); b.z = __expf(b.z); b.w = __expf(b.w);
}

// 256-bit load, L2 evict_last: pin pass-1 e stream in L2 for pass-2 reuse.
__device__ __forceinline__ void ld256_evict_last(const float* p, float4& a, float4& b) {
    uint32_t r0, r1, r2, r3, r4, r5, r6, r7;
    asm volatile("ld.global.L2::evict_last.v8.b32 {%0,%1,%2,%3,%4,%5,%6,%7}, [%8];"
                 : "=r"(r0), "=r"(r1), "=r"(r2), "=r"(r3),
                   "=r"(r4), "=r"(r5), "=r"(r6), "=r"(r7)
                 : "l"(p));
    a.x = __uint_as_float(r0); a.y = __uint_as_float(r1);
    a.z = __uint_as_float(r2); a.w = __uint_as_float(r3);
    b.x = __uint_as_float(r4); b.y = __uint_as_float(r5);
    b.z = __uint_as_float(r6); b.w = __uint_as_float(r7);
}

// 256-bit load, default policy.
__device__ __forceinline__ void ld256(const float* p, float4& a, float4& b) {
    uint32_t r0, r1, r2, r3, r4, r5, r6, r7;
    asm volatile("ld.global.v8.b32 {%0,%1,%2,%3,%4,%5,%6,%7}, [%8];"
                 : "=r"(r0), "=r"(r1), "=r"(r2), "=r"(r3),
                   "=r"(r4), "=r"(r5), "=r"(r6), "=r"(r7)
                 : "l"(p));
    a.x = __uint_as_float(r0); a.y = __uint_as_float(r1);
    a.z = __uint_as_float(r2); a.w = __uint_as_float(r3);
    b.x = __uint_as_float(r4); b.y = __uint_as_float(r5);
    b.z = __uint_as_float(r6); b.w = __uint_as_float(r7);
}

// 256-bit store, L2 evict_first: streaming output must not displace e.
__device__ __forceinline__ void st256_evict_first(float* p, float4 a, float4 b) {
    asm volatile("st.global.L2::evict_first.v8.b32 [%0], {%1,%2,%3,%4,%5,%6,%7,%8};"
                 :: "l"(p),
                    "r"(__float_as_uint(a.x)), "r"(__float_as_uint(a.y)),
                    "r"(__float_as_uint(a.z)), "r"(__float_as_uint(a.w)),
                    "r"(__float_as_uint(b.x)), "r"(__float_as_uint(b.y)),
                    "r"(__float_as_uint(b.z)), "r"(__float_as_uint(b.w))
                 : "memory");
}

// Pass 1: red-add exp(e) into g_sums[dst]. Warp-strided 2-edge batching,
// loads front-batched; REDs are fire-and-forget.
__global__ __launch_bounds__(256, 6)
void scatter_sum_kernel(const float* __restrict__ e,
                        const int* __restrict__ dst,
                        int E) {
    int base = blockIdx.x * (blockDim.x * UNROLL) + threadIdx.x;

    int d[UNROLL];
    float4 va[UNROLL], vb[UNROLL];
#pragma unroll
    for (int k = 0; k < UNROLL; k++) {
        int i = base + k * blockDim.x;
        if (i < E) {
            d[k] = __ldcs(dst + i);
            ld256_evict_last(e + (size_t)i * HEADS, va[k], vb[k]);
        }
    }
#pragma unroll
    for (int k = 0; k < UNROLL; k++) {
        int i = base + k * blockDim.x;
        if (i < E) {
            float4 a = va[k], b = vb[k];
            exp8(a, b);
            float* srow = g_sums + (size_t)d[k] * HEADS;
            asm volatile("red.global.add.v4.f32 [%0], {%1, %2, %3, %4};"
                         :: "l"(srow), "f"(a.x), "f"(a.y), "f"(a.z), "f"(a.w) : "memory");
            asm volatile("red.global.add.v4.f32 [%0], {%1, %2, %3, %4};"
                         :: "l"(srow + 4), "f"(b.x), "f"(b.y), "f"(b.z), "f"(b.w) : "memory");
        }
    }
}

// Pass 2: out = exp(e) * fast_rcp(sums[dst] + eps). idx, e AND sums gathers all
// front-batched (sums rows are 32B-aligned -> 256-bit gathers). Reverse block
// order so the earliest reads hit the L2-resident tail of e left by pass 1.
__global__ __launch_bounds__(256, 6)
void normalize_kernel(const float* __restrict__ e,
                      const int* __restrict__ dst,
                      float* __restrict__ out,
                      int E, int nBlocks) {
    int rb = nBlocks - 1 - blockIdx.x;
    int base = rb * ((int)blockDim.x * UNROLL) + threadIdx.x;

    int d[UNROLL];
#pragma unroll
    for (int k = 0; k < UNROLL; k++) {
        int i = base + k * blockDim.x;
        if (i < E) d[k] = __ldcs(dst + i);
    }

    float4 va[UNROLL], vb[UNROLL], sa[UNROLL], sb[UNROLL];
#pragma unroll
    for (int k = 0; k < UNROLL; k++) {
        int i = base + k * blockDim.x;
        if (i < E) {
            ld256(e + (size_t)i * HEADS, va[k], vb[k]);       // streaming read
            ld256(g_sums + (size_t)d[k] * HEADS, sa[k], sb[k]); // L2 gather
        }
    }

    const float eps = 1e-16f;
#pragma unroll
    for (int k = 0; k < UNROLL; k++) {
        int i = base + k * blockDim.x;
        if (i < E) {
            float4 a = va[k], b = vb[k];
            exp8(a, b);
            float4 s0 = sa[k], s1 = sb[k], o0, o1;
            o0.x = __fdividef(a.x, s0.x + eps); o0.y = __fdividef(a.y, s0.y + eps);
            o0.z = __fdividef(a.z, s0.z + eps); o0.w = __fdividef(a.w, s0.w + eps);
            o1.x = __fdividef(b.x, s1.x + eps); o1.y = __fdividef(b.y, s1.y + eps);
            o1.z = __fdividef(b.z, s1.z + eps); o1.w = __fdividef(b.w, s1.w + eps);
            st256_evict_first(out + (size_t)i * HEADS, o0, o1);
        }
    }
}

extern "C" void kernel_launch(void* const* d_in, const int* in_sizes, int n_in,
                              void* d_out, int out_size) {
    const float* e = (const float*)d_in[0];
    const int* edge_index = (const int*)d_in[1];
    int E = in_sizes[0] / HEADS;
    const int* dst = edge_index + (size_t)E;  // edge_index[1]
    float* out = (float*)d_out;

    // Zero g_sums via a memset graph node.
    void* sums_ptr = nullptr;
    cudaGetSymbolAddress(&sums_ptr, g_sums);
    cudaMemsetAsync(sums_ptr, 0, (size_t)N_NODES * HEADS * sizeof(float));

    const int T = 256;
    int perBlock = T * UNROLL;
    int nBlocks = (E + perBlock - 1) / perBlock;

    scatter_sum_kernel<<<nBlocks, T>>>(e, dst, E);
    normalize_kernel<<<nBlocks, T>>>(e, dst, out, E, nBlocks);
}

// round 12
// speedup vs baseline: 1.4035x; 1.0080x over previous
#include <cuda_runtime.h>
#include <cuda_fp16.h>
#include <cuda_bf16.h>
#include <cstdint>

#define N_NODES 100000
#define HEADS   8
#define UNROLL  2

// Per-(node, head) sum of exp(e); converted in-place to reciprocals between
// passes. 3.2 MB (L2-resident). Zeroed by memset node.
__device__ float g_sums[N_NODES * HEADS];

__device__ __forceinline__ void exp8(float4& a, float4& b) {
    a.x = __expf(a.x); a.y = __expf(a.y); a.z = __expf(a.z); a.w = __expf(a.w);
    b.x = __expf(b.x); b.y = __expf(b.y); b.z = __expf(b.z); b.w = __expf(b.w);
}

// 256-bit load, L2 evict_last: pin pass-1 e stream in L2 for pass-2 reuse.
__device__ __forceinline__ void ld256_evict_last(const float* p, float4& a, float4& b) {
    uint32_t r0, r1, r2, r3, r4, r5, r6, r7;
    asm volatile("ld.global.L2::evict_last.v8.b32 {%0,%1,%2,%3,%4,%5,%6,%7}, [%8];"
                 : "=r"(r0), "=r"(r1), "=r"(r2), "=r"(r3),
                   "=r"(r4), "=r"(r5), "=r"(r6), "=r"(r7)
                 : "l"(p));
    a.x = __uint_as_float(r0); a.y = __uint_as_float(r1);
    a.z = __uint_as_float(r2); a.w = __uint_as_float(r3);
    b.x = __uint_as_float(r4); b.y = __uint_as_float(r5);
    b.z = __uint_as_float(r6); b.w = __uint_as_float(r7);
}

// 256-bit load, default policy.
__device__ __forceinline__ void ld256(const float* p, float4& a, float4& b) {
    uint32_t r0, r1, r2, r3, r4, r5, r6, r7;
    asm volatile("ld.global.v8.b32 {%0,%1,%2,%3,%4,%5,%6,%7}, [%8];"
                 : "=r"(r0), "=r"(r1), "=r"(r2), "=r"(r3),
                   "=r"(r4), "=r"(r5), "=r"(r6), "=r"(r7)
                 : "l"(p));
    a.x = __uint_as_float(r0); a.y = __uint_as_float(r1);
    a.z = __uint_as_float(r2); a.w = __uint_as_float(r3);
    b.x = __uint_as_float(r4); b.y = __uint_as_float(r5);
    b.z = __uint_as_float(r6); b.w = __uint_as_float(r7);
}

// 256-bit store, L2 evict_first: streaming output must not displace e.
__device__ __forceinline__ void st256_evict_first(float* p, float4 a, float4 b) {
    asm volatile("st.global.L2::evict_first.v8.b32 [%0], {%1,%2,%3,%4,%5,%6,%7,%8};"
                 :: "l"(p),
                    "r"(__float_as_uint(a.x)), "r"(__float_as_uint(a.y)),
                    "r"(__float_as_uint(a.z)), "r"(__float_as_uint(a.w)),
                    "r"(__float_as_uint(b.x)), "r"(__float_as_uint(b.y)),
                    "r"(__float_as_uint(b.z)), "r"(__float_as_uint(b.w))
                 : "memory");
}

// Pass 1: red-add exp(e) into g_sums[dst]. Warp-strided 2-edge batching.
// dst loads use DEFAULT policy so the 12.8 MB idx array stays in L2 for pass 2.
__global__ __launch_bounds__(256, 6)
void scatter_sum_kernel(const float* __restrict__ e,
                        const int* __restrict__ dst,
                        int E) {
    int base = blockIdx.x * (blockDim.x * UNROLL) + threadIdx.x;

    int d[UNROLL];
    float4 va[UNROLL], vb[UNROLL];
#pragma unroll
    for (int k = 0; k < UNROLL; k++) {
        int i = base + k * blockDim.x;
        if (i < E) {
            d[k] = dst[i];
            ld256_evict_last(e + (size_t)i * HEADS, va[k], vb[k]);
        }
    }
#pragma unroll
    for (int k = 0; k < UNROLL; k++) {
        int i = base + k * blockDim.x;
        if (i < E) {
            float4 a = va[k], b = vb[k];
            exp8(a, b);
            float* srow = g_sums + (size_t)d[k] * HEADS;
            asm volatile("red.global.add.v4.f32 [%0], {%1, %2, %3, %4};"
                         :: "l"(srow), "f"(a.x), "f"(a.y), "f"(a.z), "f"(a.w) : "memory");
            asm volatile("red.global.add.v4.f32 [%0], {%1, %2, %3, %4};"
                         :: "l"(srow + 4), "f"(b.x), "f"(b.y), "f"(b.z), "f"(b.w) : "memory");
        }
    }
}

// Between passes: g_sums[i] = 1 / (g_sums[i] + eps), in place. 800K elements,
// fully L2-resident. Hoists the per-edge divide out of pass 2 (each node row
// is gathered ~32x; one reciprocal instead of 32).
__global__ __launch_bounds__(256)
void recip_kernel(int n4) {
    int i = blockIdx.x * blockDim.x + threadIdx.x;
    if (i >= n4) return;
    const float eps = 1e-16f;
    float4 s = reinterpret_cast<const float4*>(g_sums)[i];
    s.x = __fdividef(1.0f, s.x + eps);
    s.y = __fdividef(1.0f, s.y + eps);
    s.z = __fdividef(1.0f, s.z + eps);
    s.w = __fdividef(1.0f, s.w + eps);
    reinterpret_cast<float4*>(g_sums)[i] = s;
}

// Pass 2: out = exp(e) * rcp[dst]. Pure multiply (no MUFU divide). Reverse
// block order so the earliest reads hit the L2-resident tail of e.
__global__ __launch_bounds__(256, 6)
void normalize_kernel(const float* __restrict__ e,
                      const int* __restrict__ dst,
                      float* __restrict__ out,
                      int E, int nBlocks) {
    int rb = nBlocks - 1 - blockIdx.x;
    int base = rb * ((int)blockDim.x * UNROLL) + threadIdx.x;

    int d[UNROLL];
#pragma unroll
    for (int k = 0; k < UNROLL; k++) {
        int i = base + k * blockDim.x;
        if (i < E) d[k] = dst[i];
    }

    float4 va[UNROLL], vb[UNROLL], sa[UNROLL], sb[UNROLL];
#pragma unroll
    for (int k = 0; k < UNROLL; k++) {
        int i = base + k * blockDim.x;
        if (i < E) {
            ld256(e + (size_t)i * HEADS, va[k], vb[k]);         // streaming read
            ld256(g_sums + (size_t)d[k] * HEADS, sa[k], sb[k]); // L2 gather (reciprocals)
        }
    }

#pragma unroll
    for (int k = 0; k < UNROLL; k++) {
        int i = base + k * blockDim.x;
        if (i < E) {
            float4 a = va[k], b = vb[k];
            exp8(a, b);
            float4 s0 = sa[k], s1 = sb[k], o0, o1;
            o0.x = a.x * s0.x; o0.y = a.y * s0.y;
            o0.z = a.z * s0.z; o0.w = a.w * s0.w;
            o1.x = b.x * s1.x; o1.y = b.y * s1.y;
            o1.z = b.z * s1.z; o1.w = b.w * s1.w;
            st256_evict_first(out + (size_t)i * HEADS, o0, o1);
        }
    }
}

extern "C" void kernel_launch(void* const* d_in, const int* in_sizes, int n_in,
                              void* d_out, int out_size) {
    const float* e = (const float*)d_in[0];
    const int* edge_index = (const int*)d_in[1];
    int E = in_sizes[0] / HEADS;
    const int* dst = edge_index + (size_t)E;  // edge_index[1]
    float* out = (float*)d_out;

    // Zero g_sums via a memset graph node.
    void* sums_ptr = nullptr;
    cudaGetSymbolAddress(&sums_ptr, g_sums);
    cudaMemsetAsync(sums_ptr, 0, (size_t)N_NODES * HEADS * sizeof(float));

    const int T = 256;
    int perBlock = T * UNROLL;
    int nBlocks = (E + perBlock - 1) / perBlock;
    int n4 = N_NODES * HEADS / 4;

    scatter_sum_kernel<<<nBlocks, T>>>(e, dst, E);
    recip_kernel<<<(n4 + T - 1) / T, T>>>(n4);
    normalize_kernel<<<nBlocks, T>>>(e, dst, out, E, nBlocks);
}